// round 6
// baseline (speedup 1.0000x reference)
#include <cuda_runtime.h>
#include <cuda_bf16.h>
#include <math.h>
#include <stdint.h>

// Problem constants
#define BB 4
#define TT 8192
#define DDIM 512
#define HH 8
#define DH 64
#define MM (BB*TT)     // 32768 rows
#define NCHUNK 32      // T-chunks for context reduction

// GEMM config: 128x128 CTA tile, KC=64 bf16 per chunk, 512 threads, 3 stages
#define KC 64
#define NCH (DDIM/KC)            // 8
#define TILEB (128*128)          // 16384 B per 128row x 128B tile
#define AHI 0
#define ALO TILEB
#define BHI (2*TILEB)
#define BLO (3*TILEB)
#define STAGEB (4*TILEB)         // 65536
#define NSTAGE 3
#define GEMM_SMEM (NSTAGE*STAGEB) // 196608

// Scratch (device globals: no cudaMalloc allowed)
__device__ float g_qh[(size_t)MM*DDIM];
__device__ float g_kh[(size_t)MM*DDIM];
__device__ float g_vh[(size_t)MM*DDIM];
__device__ float g_ctx[BB*HH*DH*DH];
__device__ float g_ksum[BB*HH*DH];
__device__ __nv_bfloat16 g_whi[4][DDIM*DDIM];
__device__ __nv_bfloat16 g_wlo[4][DDIM*DDIM];
__device__ __nv_bfloat16 g_xhi[4][(size_t)MM*DDIM];  // 0,1,2 = q,k,v ; 3 = att
__device__ __nv_bfloat16 g_xlo[4][(size_t)MM*DDIM];

// ---------------------------------------------------------------------------
// helpers
// ---------------------------------------------------------------------------
__device__ __forceinline__ uint32_t smem_u32(const void* p) {
    uint32_t a;
    asm("{ .reg .u64 t; cvta.to.shared.u64 t, %1; cvt.u32.u64 %0, t; }" : "=r"(a) : "l"(p));
    return a;
}
__device__ __forceinline__ void ldsm4(uint32_t* r, uint32_t addr) {
    asm volatile("ldmatrix.sync.aligned.m8n8.x4.shared.b16 {%0,%1,%2,%3}, [%4];"
                 : "=r"(r[0]), "=r"(r[1]), "=r"(r[2]), "=r"(r[3]) : "r"(addr));
}
__device__ __forceinline__ void mma_bf16(float* c, const uint32_t* a, const uint32_t* b) {
    asm volatile("mma.sync.aligned.m16n8k16.row.col.f32.bf16.bf16.f32 "
                 "{%0,%1,%2,%3}, {%4,%5,%6,%7}, {%8,%9}, {%0,%1,%2,%3};"
                 : "+f"(c[0]), "+f"(c[1]), "+f"(c[2]), "+f"(c[3])
                 : "r"(a[0]), "r"(a[1]), "r"(a[2]), "r"(a[3]), "r"(b[0]), "r"(b[1]));
}
__device__ __forceinline__ void cpasync16(uint32_t dst, const void* src) {
    asm volatile("cp.async.cg.shared.global [%0], [%1], 16;" :: "r"(dst), "l"(src) : "memory");
}
__device__ __forceinline__ void cp_commit() {
    asm volatile("cp.async.commit_group;" ::: "memory");
}
__device__ __forceinline__ void cp_wait1() {
    asm volatile("cp.async.wait_group 1;" ::: "memory");
}
__device__ __forceinline__ void cp_wait0() {
    asm volatile("cp.async.wait_group 0;" ::: "memory");
}
// packs: high half = hi_f, low half = lo_f (memory order: lo first)
__device__ __forceinline__ uint32_t cvt_bf16x2(float hi_f, float lo_f) {
    uint32_t r;
    asm("cvt.rn.bf16x2.f32 %0, %1, %2;" : "=r"(r) : "f"(hi_f), "f"(lo_f));
    return r;
}
__device__ __forceinline__ void cvt_hl(float4 v, uint2& hi, uint2& lo) {
    uint32_t h01 = cvt_bf16x2(v.y, v.x);
    uint32_t h23 = cvt_bf16x2(v.w, v.z);
    float fx = __uint_as_float(h01 << 16);
    float fy = __uint_as_float(h01 & 0xFFFF0000u);
    float fz = __uint_as_float(h23 << 16);
    float fw = __uint_as_float(h23 & 0xFFFF0000u);
    hi.x = h01; hi.y = h23;
    lo.x = cvt_bf16x2(v.y - fy, v.x - fx);
    lo.y = cvt_bf16x2(v.w - fw, v.z - fz);
}

// ---------------------------------------------------------------------------
// Pre-convert: weights (4x) and activations q,k,v (3x) to bf16 hi/lo
// ---------------------------------------------------------------------------
__global__ void precvt_w(const float* __restrict__ Wq, const float* __restrict__ Wk,
                         const float* __restrict__ Wv, const float* __restrict__ Wo)
{
    const int idx = blockIdx.x * blockDim.x + threadIdx.x;
    const int w = blockIdx.y;
    const float* src = (w == 0) ? Wq : (w == 1) ? Wk : (w == 2) ? Wv : Wo;
    float4 v = *(const float4*)(src + (size_t)idx * 4);
    uint2 h, l;
    cvt_hl(v, h, l);
    *(uint2*)((char*)g_whi[w] + (size_t)idx * 8) = h;
    *(uint2*)((char*)g_wlo[w] + (size_t)idx * 8) = l;
}
__global__ void precvt_x(const float* __restrict__ q, const float* __restrict__ k,
                         const float* __restrict__ v)
{
    const size_t idx = (size_t)blockIdx.x * blockDim.x + threadIdx.x;
    const int w = blockIdx.y;
    const float* src = (w == 0) ? q : (w == 1) ? k : v;
    float4 val = *(const float4*)(src + idx * 4);
    uint2 h, l;
    cvt_hl(val, h, l);
    *(uint2*)((char*)g_xhi[w] + idx * 8) = h;
    *(uint2*)((char*)g_xlo[w] + idx * 8) = l;
}

// ---------------------------------------------------------------------------
// GEMM: Y[m,n] = sum_k X[m,k]*W[n,k] + bias[n]  (optionally elu(x)+1)
// 128x128 CTA, 512 threads (4x4 warps, warp tile 32x32), hi/lo bf16 3-MMA.
// Both operands stream via cp.async from pre-converted bf16 hi/lo globals.
// zbase=0: z=blockIdx.z in {0,1,2} -> q/k/v projections. zbase=3: final.
// ---------------------------------------------------------------------------
__global__ void __launch_bounds__(512)
gemm_mma(int zbase, const float* __restrict__ b0, const float* __restrict__ b1,
         const float* __restrict__ b2, float* __restrict__ Yout)
{
    extern __shared__ char smem[];
    const int z = zbase + blockIdx.z;
    const __nv_bfloat16* xhi = g_xhi[z];
    const __nv_bfloat16* xlo = g_xlo[z];
    const __nv_bfloat16* whi = g_whi[z];
    const __nv_bfloat16* wlo = g_wlo[z];
    const float* bias = (blockIdx.z == 0) ? b0 : (blockIdx.z == 1) ? b1 : b2;
    float* Y = (z == 0) ? g_qh : (z == 1) ? g_kh : (z == 2) ? g_vh : Yout;
    const int act = (z < 2);

    const uint32_t sb = smem_u32(smem);
    const int tid = threadIdx.x;
    const int wid = tid >> 5, lane = tid & 31;
    const int wm = wid >> 2, wn = wid & 3;       // 4 x 4 warp grid
    const int g = lane >> 2, tg = lane & 3;
    const int m0 = blockIdx.y * 128, n0 = blockIdx.x * 128;

    float acc[2][4][4];
#pragma unroll
    for (int i = 0; i < 2; i++)
#pragma unroll
        for (int j = 0; j < 4; j++)
#pragma unroll
            for (int r = 0; r < 4; r++) acc[i][j][r] = 0.f;

    // copy mapping (shared by all four tiles)
    const int cf0 = tid, cf1 = 512 + tid;
    const int cr0 = cf0 >> 3, cu0 = cf0 & 7;
    const int cr1 = cf1 >> 3, cu1 = cf1 & 7;
    const uint32_t sw0 = (uint32_t)(cr0 * 128 + ((cu0 ^ (cr0 & 7)) << 4));
    const uint32_t sw1 = (uint32_t)(cr1 * 128 + ((cu1 ^ (cr1 & 7)) << 4));
    const char* pxa0 = (const char*)(xhi + (size_t)(m0 + cr0) * DDIM) + cu0 * 16;
    const char* pxa1 = (const char*)(xhi + (size_t)(m0 + cr1) * DDIM) + cu1 * 16;
    const char* pxl0 = (const char*)(xlo + (size_t)(m0 + cr0) * DDIM) + cu0 * 16;
    const char* pxl1 = (const char*)(xlo + (size_t)(m0 + cr1) * DDIM) + cu1 * 16;
    const char* pwh0 = (const char*)(whi + (size_t)(n0 + cr0) * DDIM) + cu0 * 16;
    const char* pwh1 = (const char*)(whi + (size_t)(n0 + cr1) * DDIM) + cu1 * 16;
    const char* pwl0 = (const char*)(wlo + (size_t)(n0 + cr0) * DDIM) + cu0 * 16;
    const char* pwl1 = (const char*)(wlo + (size_t)(n0 + cr1) * DDIM) + cu1 * 16;

    auto issue = [&](int stage, int kc) {
        const uint32_t stb = sb + stage * STAGEB;
        const int kb = kc * KC * 2;  // byte offset along K
        cpasync16(stb + AHI + sw0, pxa0 + kb);
        cpasync16(stb + AHI + sw1, pxa1 + kb);
        cpasync16(stb + ALO + sw0, pxl0 + kb);
        cpasync16(stb + ALO + sw1, pxl1 + kb);
        cpasync16(stb + BHI + sw0, pwh0 + kb);
        cpasync16(stb + BHI + sw1, pwh1 + kb);
        cpasync16(stb + BLO + sw0, pwl0 + kb);
        cpasync16(stb + BLO + sw1, pwl1 + kb);
        cp_commit();
    };

    // prologue: stages 0,1 <- chunks 0,1
    issue(0, 0);
    issue(1, 1);

    for (int kc = 0; kc < NCH; kc++) {
        if (kc < NCH - 1) cp_wait1(); else cp_wait0();
        __syncthreads();
        if (kc + 2 < NCH) issue((kc + 2) % NSTAGE, kc + 2);

        const uint32_t st = sb + (kc % NSTAGE) * STAGEB;
#pragma unroll
        for (int ks = 0; ks < 4; ks++) {
            uint32_t ah[2][4], al[2][4];
#pragma unroll
            for (int mi = 0; mi < 2; mi++) {
                int rA = wm * 32 + mi * 16 + (lane & 15);
                int cA = ks * 2 + (lane >> 4);
                uint32_t ad = st + AHI + rA * 128 + ((cA ^ (rA & 7)) << 4);
                ldsm4(ah[mi], ad);
                ldsm4(al[mi], ad + TILEB);
            }
            uint32_t bh[4][2], bl[4][2];
#pragma unroll
            for (int np = 0; np < 2; np++) {
                int rB = wn * 32 + np * 16 + ((lane >> 4) << 3) + (lane & 7);
                int cB = ks * 2 + ((lane >> 3) & 1);
                uint32_t bd = st + BHI + rB * 128 + ((cB ^ (rB & 7)) << 4);
                uint32_t r4[4];
                ldsm4(r4, bd);
                bh[np*2][0] = r4[0]; bh[np*2][1] = r4[1];
                bh[np*2+1][0] = r4[2]; bh[np*2+1][1] = r4[3];
                ldsm4(r4, bd + TILEB);
                bl[np*2][0] = r4[0]; bl[np*2][1] = r4[1];
                bl[np*2+1][0] = r4[2]; bl[np*2+1][1] = r4[3];
            }
#pragma unroll
            for (int mi = 0; mi < 2; mi++)
#pragma unroll
                for (int ni = 0; ni < 4; ni++) {
                    mma_bf16(acc[mi][ni], ah[mi], bh[ni]);
                    mma_bf16(acc[mi][ni], ah[mi], bl[ni]);
                    mma_bf16(acc[mi][ni], al[mi], bh[ni]);
                }
        }
        __syncthreads();
    }

    // epilogue: bias + optional elu+1
#pragma unroll
    for (int mi = 0; mi < 2; mi++) {
#pragma unroll
        for (int ni = 0; ni < 4; ni++) {
            const int col = n0 + wn * 32 + ni * 8 + tg * 2;
            const float b0v = bias[col], b1v = bias[col + 1];
#pragma unroll
            for (int half = 0; half < 2; half++) {
                const int row = m0 + wm * 32 + mi * 16 + g + half * 8;
                float2 o;
                o.x = acc[mi][ni][half * 2 + 0] + b0v;
                o.y = acc[mi][ni][half * 2 + 1] + b1v;
                if (act) {
                    o.x = (o.x > 0.f) ? o.x + 1.f : expf(o.x);
                    o.y = (o.y > 0.f) ? o.y + 1.f : expf(o.y);
                }
                *(float2*)(Y + (size_t)row * DDIM + col) = o;
            }
        }
    }
}

// ---------------------------------------------------------------------------
// Zero accumulators
// ---------------------------------------------------------------------------
__global__ void zero_kernel()
{
    int i = blockIdx.x * blockDim.x + threadIdx.x;
    if (i < BB*HH*DH*DH) g_ctx[i]  = 0.f;
    if (i < BB*HH*DH)    g_ksum[i] = 0.f;
}

// ---------------------------------------------------------------------------
// Context reduction: ctx[b,h,c,d] = sum_t kh*vh ; ksum[b,h,c] = sum_t kh
// ---------------------------------------------------------------------------
__global__ __launch_bounds__(256)
void ctx_kernel()
{
    const int bh = blockIdx.x;
    const int chunk = blockIdx.y;
    const int b = bh >> 3, h = bh & 7;

    __shared__ float ks[32][64];
    __shared__ float vs[32][64];

    const int tid = threadIdx.x;
    const int cb = tid >> 4;
    const int db = tid & 15;

    float acc[4][4];
#pragma unroll
    for (int i = 0; i < 4; i++)
#pragma unroll
        for (int j = 0; j < 4; j++) acc[i][j] = 0.f;
    float ksacc = 0.f;

    const int tbase = b*TT + chunk * (TT/NCHUNK);

    for (int tt = 0; tt < TT/NCHUNK; tt += 32) {
#pragma unroll
        for (int qq = 0; qq < 2; qq++) {
            const int fi = qq*256 + tid;
            const int r  = fi >> 4;
            const int c4 = fi & 15;
            const size_t gofs = (size_t)(tbase + tt + r) * DDIM + h*DH + c4*4;
            *(float4*)&ks[r][c4*4] = *(const float4*)(g_kh + gofs);
            *(float4*)&vs[r][c4*4] = *(const float4*)(g_vh + gofs);
        }
        __syncthreads();

        if (tid < 64) {
#pragma unroll
            for (int t = 0; t < 32; t++) ksacc += ks[t][tid];
        }

#pragma unroll 8
        for (int t = 0; t < 32; t++) {
            float4 av = *(const float4*)&ks[t][cb*4];
            float4 bv = *(const float4*)&vs[t][db*4];
            float ar[4] = {av.x, av.y, av.z, av.w};
            float br[4] = {bv.x, bv.y, bv.z, bv.w};
#pragma unroll
            for (int i = 0; i < 4; i++)
#pragma unroll
                for (int j = 0; j < 4; j++)
                    acc[i][j] += ar[i] * br[j];
        }
        __syncthreads();
    }

    float* cp = g_ctx + bh * DH * DH;
#pragma unroll
    for (int i = 0; i < 4; i++)
#pragma unroll
        for (int j = 0; j < 4; j++)
            atomicAdd(&cp[(cb*4+i)*DH + (db*4+j)], acc[i][j]);
    if (tid < 64) atomicAdd(&g_ksum[bh*DH + tid], ksacc);
}

// ---------------------------------------------------------------------------
// Apply: att = (qh @ ctx) / (qh @ ksum); writes bf16 hi/lo directly (slot 3)
// ---------------------------------------------------------------------------
__global__ __launch_bounds__(256)
void apply_kernel()
{
    const int bh = blockIdx.x;
    const int tile = blockIdx.y;
    const int b = bh >> 3, h = bh & 7;

    __shared__ float ctxs[64][68];
    __shared__ float qsm[64][68];
    __shared__ float dsm[64];

    const int tid = threadIdx.x;
    const int t0 = tile * 64;
    const float* cp = g_ctx + bh * 4096;

#pragma unroll
    for (int qq = 0; qq < 4; qq++) {
        const int fi = qq*256 + tid;
        const int r  = fi >> 4;
        const int c4 = fi & 15;
        *(float4*)&ctxs[r][c4*4] = *(const float4*)(cp + r*64 + c4*4);
        const size_t gofs = (size_t)(b*TT + t0 + r) * DDIM + h*DH + c4*4;
        *(float4*)&qsm[r][c4*4] = *(const float4*)(g_qh + gofs);
    }
    __syncthreads();

    if (tid < 64) {
        const float* kp = g_ksum + bh * DH;
        float dn = 0.f;
#pragma unroll
        for (int c = 0; c < 64; c++) dn += qsm[tid][c] * kp[c];
        dsm[tid] = dn;
    }
    __syncthreads();

    const int tsub = tid >> 4;
    const int dq   = (tid & 15) * 4;
#pragma unroll
    for (int ts = 0; ts < 4; ts++) {
        const int t = ts*16 + tsub;
        float4 acc = {0.f, 0.f, 0.f, 0.f};
#pragma unroll
        for (int c = 0; c < 64; c++) {
            const float qv = qsm[t][c];
            const float4 cv = *(const float4*)&ctxs[c][dq];
            acc.x += qv * cv.x;
            acc.y += qv * cv.y;
            acc.z += qv * cv.z;
            acc.w += qv * cv.w;
        }
        const float inv = 1.f / dsm[t];
        float4 o = {acc.x*inv, acc.y*inv, acc.z*inv, acc.w*inv};
        const size_t e = (size_t)(b*TT + t0 + t) * DDIM + h*DH + dq;
        uint2 hh, ll;
        cvt_hl(o, hh, ll);
        *(uint2*)((char*)g_xhi[3] + e * 2) = hh;
        *(uint2*)((char*)g_xlo[3] + e * 2) = ll;
    }
}

// ---------------------------------------------------------------------------
extern "C" void kernel_launch(void* const* d_in, const int* in_sizes, int n_in,
                              void* d_out, int out_size)
{
    const float* q  = (const float*)d_in[0];
    const float* k  = (const float*)d_in[1];
    const float* v  = (const float*)d_in[2];
    const float* Wq = (const float*)d_in[3];
    const float* bq = (const float*)d_in[4];
    const float* Wk = (const float*)d_in[5];
    const float* bk = (const float*)d_in[6];
    const float* Wv = (const float*)d_in[7];
    const float* bv = (const float*)d_in[8];
    const float* Wo = (const float*)d_in[9];
    const float* bo = (const float*)d_in[10];
    float* out = (float*)d_out;

    cudaFuncSetAttribute((const void*)gemm_mma,
                         cudaFuncAttributeMaxDynamicSharedMemorySize, GEMM_SMEM);

    precvt_w<<<dim3(DDIM*DDIM/4/256, 4), 256>>>(Wq, Wk, Wv, Wo);
    precvt_x<<<dim3(MM*DDIM/4/256, 3), 256>>>(q, k, v);
    zero_kernel<<<(BB*HH*DH*DH + 255)/256, 256>>>();
    gemm_mma<<<dim3(DDIM/128, MM/128, 3), 512, GEMM_SMEM>>>(0, bq, bk, bv, nullptr);
    ctx_kernel<<<dim3(BB*HH, NCHUNK), 256>>>();
    apply_kernel<<<dim3(BB*HH, TT/64), 256>>>();
    gemm_mma<<<dim3(DDIM/128, MM/128, 1), 512, GEMM_SMEM>>>(3, bo, bo, bo, out);
}

// round 7
// speedup vs baseline: 1.8225x; 1.8225x over previous
#include <cuda_runtime.h>
#include <cuda_fp16.h>
#include <math.h>
#include <stdint.h>

#define BB 4
#define TT 8192
#define DDIM 512
#define HH 8
#define DH 64
#define MM (BB*TT)
#define NCHUNK 32

#define KC 64                    // halves per K chunk (128B rows)
#define NCH (DDIM/KC)            // 8
#define TILEB (128*128)          // 16 KB tile
#define SM3 (2*4*TILEB)          // gemm3: 2 stages x (Ahi,Alo,Bhi,Blo) = 128 KB
#define SM1 (2*2*TILEB)          // gemm1: 2 stages x (A,B) = 64 KB

// Scratch
__device__ float g_qh [(size_t)MM*DDIM];
__device__ float g_att[(size_t)MM*DDIM];
__device__ __half g_khh[(size_t)MM*DDIM];
__device__ __half g_vhh[(size_t)MM*DDIM];
__device__ float g_ctx[BB*HH*DH*DH];
__device__ float g_ksum[BB*HH*DH];
__device__ __half g_w3h[2][DDIM*DDIM];   // Wq, Wo hi
__device__ __half g_w3l[2][DDIM*DDIM];   // Wq, Wo lo
__device__ __half g_w1 [2][DDIM*DDIM];   // Wk, Wv single

// ---------------- helpers ----------------
__device__ __forceinline__ uint32_t smem_u32(const void* p) {
    uint32_t a;
    asm("{ .reg .u64 t; cvta.to.shared.u64 t, %1; cvt.u32.u64 %0, t; }" : "=r"(a) : "l"(p));
    return a;
}
__device__ __forceinline__ void ldsm4(uint32_t* r, uint32_t addr) {
    asm volatile("ldmatrix.sync.aligned.m8n8.x4.shared.b16 {%0,%1,%2,%3}, [%4];"
                 : "=r"(r[0]), "=r"(r[1]), "=r"(r[2]), "=r"(r[3]) : "r"(addr));
}
__device__ __forceinline__ void mma_f16(float* c, const uint32_t* a, const uint32_t* b) {
    asm volatile("mma.sync.aligned.m16n8k16.row.col.f32.f16.f16.f32 "
                 "{%0,%1,%2,%3}, {%4,%5,%6,%7}, {%8,%9}, {%0,%1,%2,%3};"
                 : "+f"(c[0]), "+f"(c[1]), "+f"(c[2]), "+f"(c[3])
                 : "r"(a[0]), "r"(a[1]), "r"(a[2]), "r"(a[3]), "r"(b[0]), "r"(b[1]));
}
__device__ __forceinline__ void cpasync16(uint32_t dst, const void* src) {
    asm volatile("cp.async.cg.shared.global [%0], [%1], 16;" :: "r"(dst), "l"(src) : "memory");
}
__device__ __forceinline__ void cp_commit() { asm volatile("cp.async.commit_group;" ::: "memory"); }
__device__ __forceinline__ void cp_wait0()  { asm volatile("cp.async.wait_group 0;" ::: "memory"); }
__device__ __forceinline__ uint32_t swz(int r, int u) {   // 128B rows, 16B units
    return (uint32_t)(r * 128 + ((u ^ (r & 7)) << 4));
}
// fp16 hi/lo split of float4 -> 2x uint2 (memory order: .x pairs first)
__device__ __forceinline__ void cvt_hl(float4 v, uint2& hi, uint2& lo) {
    __half2 h01 = __floats2half2_rn(v.x, v.y);
    __half2 h23 = __floats2half2_rn(v.z, v.w);
    __half2 l01 = __floats2half2_rn(v.x - __low2float(h01), v.y - __high2float(h01));
    __half2 l23 = __floats2half2_rn(v.z - __low2float(h23), v.w - __high2float(h23));
    hi.x = *reinterpret_cast<uint32_t*>(&h01); hi.y = *reinterpret_cast<uint32_t*>(&h23);
    lo.x = *reinterpret_cast<uint32_t*>(&l01); lo.y = *reinterpret_cast<uint32_t*>(&l23);
}

// ---------------- pre-conversion ----------------
__global__ void precvt_w3(const float* __restrict__ Wq, const float* __restrict__ Wo) {
    const int idx = blockIdx.x * blockDim.x + threadIdx.x;
    const int w = blockIdx.y;
    float4 v = *(const float4*)(((w == 0) ? Wq : Wo) + (size_t)idx * 4);
    uint2 h, l;
    cvt_hl(v, h, l);
    *(uint2*)((char*)g_w3h[w] + (size_t)idx * 8) = h;
    *(uint2*)((char*)g_w3l[w] + (size_t)idx * 8) = l;
}
__global__ void precvt_w1(const float* __restrict__ Wk, const float* __restrict__ Wv) {
    const int idx = blockIdx.x * blockDim.x + threadIdx.x;
    const int w = blockIdx.y;
    float4 v = *(const float4*)(((w == 0) ? Wk : Wv) + (size_t)idx * 4);
    __half2 h01 = __floats2half2_rn(v.x, v.y);
    __half2 h23 = __floats2half2_rn(v.z, v.w);
    uint2 h = { *reinterpret_cast<uint32_t*>(&h01), *reinterpret_cast<uint32_t*>(&h23) };
    *(uint2*)((char*)g_w1[w] + (size_t)idx * 8) = h;
}

// ---------------- 3-term GEMM (q-proj, o-proj) ----------------
// Round-4 proven structure: A fp32 LDG->cvt hi/lo->STS; B hi/lo cp.async.
__global__ void __launch_bounds__(512)
gemm3(const float* __restrict__ Xext, int xsel, int ws,
      const float* __restrict__ bias, float* __restrict__ Yext, int ysel, int act)
{
    extern __shared__ char smem[];
    const float* X = (xsel == 1) ? g_att : Xext;
    float* Y = (ysel == 1) ? g_qh : Yext;
    const __half* whi = g_w3h[ws];
    const __half* wlo = g_w3l[ws];

    const int AHI = 0, ALO = TILEB, BHI = 2*TILEB, BLO = 3*TILEB, STAGE = 4*TILEB;
    const uint32_t sb = smem_u32(smem);
    const int tid = threadIdx.x;
    const int wid = tid >> 5, lane = tid & 31;
    const int wm = wid >> 2, wn = wid & 3;
    const int g = lane >> 2, tg = lane & 3;
    const int m0 = blockIdx.y * 128, n0 = blockIdx.x * 128;

    float acc[2][4][4];
#pragma unroll
    for (int i = 0; i < 2; i++)
#pragma unroll
        for (int j = 0; j < 4; j++)
#pragma unroll
            for (int r = 0; r < 4; r++) acc[i][j][r] = 0.f;

    float4 ra[4];
    auto ldgA = [&](int k0) {
#pragma unroll
        for (int it = 0; it < 4; it++) {
            int f = it * 512 + tid, r = f >> 4, cs = f & 15;
            ra[it] = *(const float4*)(X + (size_t)(m0 + r) * DDIM + k0 + cs * 4);
        }
    };
    auto stsA = [&](int stage) {
        char* base = smem + stage * STAGE;
#pragma unroll
        for (int it = 0; it < 4; it++) {
            int f = it * 512 + tid, r = f >> 4, cs = f & 15;
            int off = (int)swz(r, cs >> 1) + (cs & 1) * 8;
            uint2 h, l;
            cvt_hl(ra[it], h, l);
            *(uint2*)(base + AHI + off) = h;
            *(uint2*)(base + ALO + off) = l;
        }
    };
    auto issueB = [&](int stage, int kc) {
        const uint32_t stb = sb + stage * STAGE;
        const int k0 = kc * KC;
#pragma unroll
        for (int it = 0; it < 2; it++) {
            int f = it * 512 + tid, r = f >> 3, u = f & 7;
            cpasync16(stb + BHI + swz(r, u), (const char*)(whi + (size_t)(n0 + r) * DDIM + k0) + u * 16);
            cpasync16(stb + BLO + swz(r, u), (const char*)(wlo + (size_t)(n0 + r) * DDIM + k0) + u * 16);
        }
        cp_commit();
    };

    ldgA(0); issueB(0, 0); stsA(0); ldgA(KC);

    for (int kc = 0; kc < NCH; kc++) {
        const int cur = kc & 1;
        cp_wait0();
        __syncthreads();
        if (kc < NCH - 1) { issueB(1 - cur, kc + 1); stsA(1 - cur); }
        if (kc < NCH - 2) ldgA((kc + 2) * KC);

        const uint32_t st = sb + cur * STAGE;
#pragma unroll
        for (int ks = 0; ks < 4; ks++) {
            uint32_t ah[2][4], al[2][4];
#pragma unroll
            for (int mi = 0; mi < 2; mi++) {
                int rA = wm * 32 + mi * 16 + (lane & 15);
                int cA = ks * 2 + (lane >> 4);
                uint32_t ad = st + AHI + swz(rA, cA);
                ldsm4(ah[mi], ad);
                ldsm4(al[mi], ad + TILEB);
            }
            uint32_t bh[4][2], bl[4][2];
#pragma unroll
            for (int np = 0; np < 2; np++) {
                int rB = wn * 32 + np * 16 + ((lane >> 4) << 3) + (lane & 7);
                int cB = ks * 2 + ((lane >> 3) & 1);
                uint32_t bd = st + BHI + swz(rB, cB);
                uint32_t r4[4];
                ldsm4(r4, bd);
                bh[np*2][0] = r4[0]; bh[np*2][1] = r4[1];
                bh[np*2+1][0] = r4[2]; bh[np*2+1][1] = r4[3];
                ldsm4(r4, bd + TILEB);
                bl[np*2][0] = r4[0]; bl[np*2][1] = r4[1];
                bl[np*2+1][0] = r4[2]; bl[np*2+1][1] = r4[3];
            }
#pragma unroll
            for (int mi = 0; mi < 2; mi++)
#pragma unroll
                for (int ni = 0; ni < 4; ni++) {
                    mma_f16(acc[mi][ni], ah[mi], bh[ni]);
                    mma_f16(acc[mi][ni], ah[mi], bl[ni]);
                    mma_f16(acc[mi][ni], al[mi], bh[ni]);
                }
        }
        __syncthreads();
    }

#pragma unroll
    for (int mi = 0; mi < 2; mi++)
#pragma unroll
        for (int ni = 0; ni < 4; ni++) {
            const int col = n0 + wn * 32 + ni * 8 + tg * 2;
            const float b0 = bias[col], b1 = bias[col + 1];
#pragma unroll
            for (int half = 0; half < 2; half++) {
                const int row = m0 + wm * 32 + mi * 16 + g + half * 8;
                float2 o;
                o.x = acc[mi][ni][half * 2 + 0] + b0;
                o.y = acc[mi][ni][half * 2 + 1] + b1;
                if (act) {
                    o.x = (o.x > 0.f) ? o.x + 1.f : expf(o.x);
                    o.y = (o.y > 0.f) ? o.y + 1.f : expf(o.y);
                }
                *(float2*)(Y + (size_t)row * DDIM + col) = o;
            }
        }
}

// ---------------- 1-term GEMM (k-proj, v-proj) -> fp16 out ----------------
__global__ void __launch_bounds__(512, 2)
gemm1(const float* __restrict__ Xk, const float* __restrict__ Xv,
      const float* __restrict__ bk, const float* __restrict__ bv)
{
    extern __shared__ char smem[];
    const int z = blockIdx.z;
    const float* X = z ? Xv : Xk;
    const float* bias = z ? bv : bk;
    const __half* W = g_w1[z];
    __half* Y = z ? g_vhh : g_khh;
    const int act = (z == 0);

    const int AHI = 0, BHI = TILEB, STAGE = 2*TILEB;
    const uint32_t sb = smem_u32(smem);
    const int tid = threadIdx.x;
    const int wid = tid >> 5, lane = tid & 31;
    const int wm = wid >> 2, wn = wid & 3;
    const int g = lane >> 2, tg = lane & 3;
    const int m0 = blockIdx.y * 128, n0 = blockIdx.x * 128;

    float acc[2][4][4];
#pragma unroll
    for (int i = 0; i < 2; i++)
#pragma unroll
        for (int j = 0; j < 4; j++)
#pragma unroll
            for (int r = 0; r < 4; r++) acc[i][j][r] = 0.f;

    float4 ra[4];
    auto ldgA = [&](int k0) {
#pragma unroll
        for (int it = 0; it < 4; it++) {
            int f = it * 512 + tid, r = f >> 4, cs = f & 15;
            ra[it] = *(const float4*)(X + (size_t)(m0 + r) * DDIM + k0 + cs * 4);
        }
    };
    auto stsA = [&](int stage) {
        char* base = smem + stage * STAGE + AHI;
#pragma unroll
        for (int it = 0; it < 4; it++) {
            int f = it * 512 + tid, r = f >> 4, cs = f & 15;
            __half2 h01 = __floats2half2_rn(ra[it].x, ra[it].y);
            __half2 h23 = __floats2half2_rn(ra[it].z, ra[it].w);
            uint2 h = { *reinterpret_cast<uint32_t*>(&h01), *reinterpret_cast<uint32_t*>(&h23) };
            *(uint2*)(base + (int)swz(r, cs >> 1) + (cs & 1) * 8) = h;
        }
    };
    auto issueB = [&](int stage, int kc) {
        const uint32_t stb = sb + stage * STAGE + BHI;
        const int k0 = kc * KC;
#pragma unroll
        for (int it = 0; it < 2; it++) {
            int f = it * 512 + tid, r = f >> 3, u = f & 7;
            cpasync16(stb + swz(r, u), (const char*)(W + (size_t)(n0 + r) * DDIM + k0) + u * 16);
        }
        cp_commit();
    };

    ldgA(0); issueB(0, 0); stsA(0); ldgA(KC);

    for (int kc = 0; kc < NCH; kc++) {
        const int cur = kc & 1;
        cp_wait0();
        __syncthreads();
        if (kc < NCH - 1) { issueB(1 - cur, kc + 1); stsA(1 - cur); }
        if (kc < NCH - 2) ldgA((kc + 2) * KC);

        const uint32_t st = sb + cur * STAGE;
#pragma unroll
        for (int ks = 0; ks < 4; ks++) {
            uint32_t ah[2][4];
#pragma unroll
            for (int mi = 0; mi < 2; mi++) {
                int rA = wm * 32 + mi * 16 + (lane & 15);
                int cA = ks * 2 + (lane >> 4);
                ldsm4(ah[mi], st + AHI + swz(rA, cA));
            }
#pragma unroll
            for (int np = 0; np < 2; np++) {
                int rB = wn * 32 + np * 16 + ((lane >> 4) << 3) + (lane & 7);
                int cB = ks * 2 + ((lane >> 3) & 1);
                uint32_t r4[4];
                ldsm4(r4, st + BHI + swz(rB, cB));
                uint32_t b0[2] = {r4[0], r4[1]}, b1[2] = {r4[2], r4[3]};
#pragma unroll
                for (int mi = 0; mi < 2; mi++) {
                    mma_f16(acc[mi][np*2+0], ah[mi], b0);
                    mma_f16(acc[mi][np*2+1], ah[mi], b1);
                }
            }
        }
        __syncthreads();
    }

#pragma unroll
    for (int mi = 0; mi < 2; mi++)
#pragma unroll
        for (int ni = 0; ni < 4; ni++) {
            const int col = n0 + wn * 32 + ni * 8 + tg * 2;
            const float b0 = bias[col], b1 = bias[col + 1];
#pragma unroll
            for (int half = 0; half < 2; half++) {
                const int row = m0 + wm * 32 + mi * 16 + g + half * 8;
                float x = acc[mi][ni][half * 2 + 0] + b0;
                float y = acc[mi][ni][half * 2 + 1] + b1;
                if (act) {
                    x = (x > 0.f) ? x + 1.f : expf(x);
                    y = (y > 0.f) ? y + 1.f : expf(y);
                }
                __half2 h = __floats2half2_rn(x, y);
                *(uint32_t*)((char*)Y + ((size_t)row * DDIM + col) * 2) =
                    *reinterpret_cast<uint32_t*>(&h);
            }
        }
}

// ---------------- zero ----------------
__global__ void zero_kernel()
{
    int i = blockIdx.x * blockDim.x + threadIdx.x;
    if (i < BB*HH*DH*DH) g_ctx[i]  = 0.f;
    if (i < BB*HH*DH)    g_ksum[i] = 0.f;
}

// ---------------- ctx: reads fp16 kh/vh ----------------
__global__ __launch_bounds__(256)
void ctx_kernel()
{
    const int bh = blockIdx.x;
    const int chunk = blockIdx.y;
    const int b = bh >> 3, h = bh & 7;

    __shared__ float ks[32][64];
    __shared__ float vs[32][64];

    const int tid = threadIdx.x;
    const int cb = tid >> 4;
    const int db = tid & 15;

    float acc[4][4];
#pragma unroll
    for (int i = 0; i < 4; i++)
#pragma unroll
        for (int j = 0; j < 4; j++) acc[i][j] = 0.f;
    float ksacc = 0.f;

    const int tbase = b*TT + chunk * (TT/NCHUNK);

    for (int tt = 0; tt < TT/NCHUNK; tt += 32) {
#pragma unroll
        for (int qq = 0; qq < 2; qq++) {
            const int fi = qq*256 + tid;
            const int r  = fi >> 4;
            const int c4 = fi & 15;
            const size_t gofs = (size_t)(tbase + tt + r) * DDIM + h*DH + c4*4;
            uint2 kw = *(const uint2*)((const char*)g_khh + gofs*2);
            uint2 vw = *(const uint2*)((const char*)g_vhh + gofs*2);
            float2 k0 = __half22float2(*reinterpret_cast<__half2*>(&kw.x));
            float2 k1 = __half22float2(*reinterpret_cast<__half2*>(&kw.y));
            float2 v0 = __half22float2(*reinterpret_cast<__half2*>(&vw.x));
            float2 v1 = __half22float2(*reinterpret_cast<__half2*>(&vw.y));
            ks[r][c4*4+0]=k0.x; ks[r][c4*4+1]=k0.y; ks[r][c4*4+2]=k1.x; ks[r][c4*4+3]=k1.y;
            vs[r][c4*4+0]=v0.x; vs[r][c4*4+1]=v0.y; vs[r][c4*4+2]=v1.x; vs[r][c4*4+3]=v1.y;
        }
        __syncthreads();

        if (tid < 64) {
#pragma unroll
            for (int t = 0; t < 32; t++) ksacc += ks[t][tid];
        }

#pragma unroll 8
        for (int t = 0; t < 32; t++) {
            float4 av = *(const float4*)&ks[t][cb*4];
            float4 bv = *(const float4*)&vs[t][db*4];
            float ar[4] = {av.x, av.y, av.z, av.w};
            float br[4] = {bv.x, bv.y, bv.z, bv.w};
#pragma unroll
            for (int i = 0; i < 4; i++)
#pragma unroll
                for (int j = 0; j < 4; j++)
                    acc[i][j] += ar[i] * br[j];
        }
        __syncthreads();
    }

    float* cp = g_ctx + bh * DH * DH;
#pragma unroll
    for (int i = 0; i < 4; i++)
#pragma unroll
        for (int j = 0; j < 4; j++)
            atomicAdd(&cp[(cb*4+i)*DH + (db*4+j)], acc[i][j]);
    if (tid < 64) atomicAdd(&g_ksum[bh*DH + tid], ksacc);
}

// ---------------- apply: att = (qh@ctx)/(qh@ksum) ----------------
__global__ __launch_bounds__(256)
void apply_kernel()
{
    const int bh = blockIdx.x;
    const int tile = blockIdx.y;
    const int b = bh >> 3, h = bh & 7;

    __shared__ float ctxs[64][68];
    __shared__ float qsm[64][68];
    __shared__ float dsm[64];

    const int tid = threadIdx.x;
    const int t0 = tile * 64;
    const float* cp = g_ctx + bh * 4096;

#pragma unroll
    for (int qq = 0; qq < 4; qq++) {
        const int fi = qq*256 + tid;
        const int r  = fi >> 4;
        const int c4 = fi & 15;
        *(float4*)&ctxs[r][c4*4] = *(const float4*)(cp + r*64 + c4*4);
        const size_t gofs = (size_t)(b*TT + t0 + r) * DDIM + h*DH + c4*4;
        *(float4*)&qsm[r][c4*4] = *(const float4*)(g_qh + gofs);
    }
    __syncthreads();

    if (tid < 64) {
        const float* kp = g_ksum + bh * DH;
        float dn = 0.f;
#pragma unroll
        for (int c = 0; c < 64; c++) dn += qsm[tid][c] * kp[c];
        dsm[tid] = dn;
    }
    __syncthreads();

    const int tsub = tid >> 4;
    const int dq   = (tid & 15) * 4;
#pragma unroll
    for (int ts = 0; ts < 4; ts++) {
        const int t = ts*16 + tsub;
        float4 acc = {0.f, 0.f, 0.f, 0.f};
#pragma unroll
        for (int c = 0; c < 64; c++) {
            const float qv = qsm[t][c];
            const float4 cv = *(const float4*)&ctxs[c][dq];
            acc.x += qv * cv.x;
            acc.y += qv * cv.y;
            acc.z += qv * cv.z;
            acc.w += qv * cv.w;
        }
        const float inv = 1.f / dsm[t];
        float4 o = {acc.x*inv, acc.y*inv, acc.z*inv, acc.w*inv};
        const size_t gofs = (size_t)(b*TT + t0 + t) * DDIM + h*DH + dq;
        *(float4*)(g_att + gofs) = o;
    }
}

// ---------------- launch ----------------
extern "C" void kernel_launch(void* const* d_in, const int* in_sizes, int n_in,
                              void* d_out, int out_size)
{
    const float* q  = (const float*)d_in[0];
    const float* k  = (const float*)d_in[1];
    const float* v  = (const float*)d_in[2];
    const float* Wq = (const float*)d_in[3];
    const float* bq = (const float*)d_in[4];
    const float* Wk = (const float*)d_in[5];
    const float* bk = (const float*)d_in[6];
    const float* Wv = (const float*)d_in[7];
    const float* bv = (const float*)d_in[8];
    const float* Wo = (const float*)d_in[9];
    const float* bo = (const float*)d_in[10];
    float* out = (float*)d_out;

    cudaFuncSetAttribute((const void*)gemm3, cudaFuncAttributeMaxDynamicSharedMemorySize, SM3);
    cudaFuncSetAttribute((const void*)gemm1, cudaFuncAttributeMaxDynamicSharedMemorySize, SM1);

    precvt_w3<<<dim3(256, 2), 256>>>(Wq, Wo);
    precvt_w1<<<dim3(256, 2), 256>>>(Wk, Wv);
    zero_kernel<<<(BB*HH*DH*DH + 255)/256, 256>>>();
    gemm3<<<dim3(4, 256), 512, SM3>>>(q, 0, 0, bq, nullptr, 1, 1);     // qh (3-term)
    gemm1<<<dim3(4, 256, 2), 512, SM1>>>(k, v, bk, bv);                // kh, vh (1-term fp16)
    ctx_kernel<<<dim3(BB*HH, NCHUNK), 256>>>();
    apply_kernel<<<dim3(BB*HH, TT/64), 256>>>();
    gemm3<<<dim3(4, 256), 512, SM3>>>(nullptr, 1, 1, bo, out, 0, 0);   // out (3-term)
}

// round 8
// speedup vs baseline: 1.9985x; 1.0966x over previous
#include <cuda_runtime.h>
#include <cuda_fp16.h>
#include <math.h>
#include <stdint.h>

#define BB 4
#define TT 8192
#define DDIM 512
#define HH 8
#define DH 64
#define MM (BB*TT)
#define NCHUNK 32

#define KC 64                    // halves per K chunk (128B rows)
#define NCH (DDIM/KC)            // 8
#define TILEB (128*128)          // 16 KB tile
#define SM3 (2*4*TILEB)          // gemm3: 2 stages x (Ahi,Alo,Bhi,Blo) = 128 KB
#define SM1 (2*2*TILEB)          // gemm1: 2 stages x (A,B) = 64 KB

// Scratch
__device__ float g_att[(size_t)MM*DDIM];
__device__ __half g_qhh[(size_t)MM*DDIM];
__device__ __half g_khh[(size_t)MM*DDIM];
__device__ __half g_vhh[(size_t)MM*DDIM];
__device__ float g_ctx[BB*HH*DH*DH];
__device__ float g_ksum[BB*HH*DH];
__device__ __half g_w3h[DDIM*DDIM];      // Wo hi
__device__ __half g_w3l[DDIM*DDIM];      // Wo lo
__device__ __half g_w1[3][DDIM*DDIM];    // Wq, Wk, Wv single fp16

// ---------------- helpers ----------------
__device__ __forceinline__ uint32_t smem_u32(const void* p) {
    uint32_t a;
    asm("{ .reg .u64 t; cvta.to.shared.u64 t, %1; cvt.u32.u64 %0, t; }" : "=r"(a) : "l"(p));
    return a;
}
__device__ __forceinline__ void ldsm4(uint32_t* r, uint32_t addr) {
    asm volatile("ldmatrix.sync.aligned.m8n8.x4.shared.b16 {%0,%1,%2,%3}, [%4];"
                 : "=r"(r[0]), "=r"(r[1]), "=r"(r[2]), "=r"(r[3]) : "r"(addr));
}
__device__ __forceinline__ void mma_f16(float* c, const uint32_t* a, const uint32_t* b) {
    asm volatile("mma.sync.aligned.m16n8k16.row.col.f32.f16.f16.f32 "
                 "{%0,%1,%2,%3}, {%4,%5,%6,%7}, {%8,%9}, {%0,%1,%2,%3};"
                 : "+f"(c[0]), "+f"(c[1]), "+f"(c[2]), "+f"(c[3])
                 : "r"(a[0]), "r"(a[1]), "r"(a[2]), "r"(a[3]), "r"(b[0]), "r"(b[1]));
}
__device__ __forceinline__ void cpasync16(uint32_t dst, const void* src) {
    asm volatile("cp.async.cg.shared.global [%0], [%1], 16;" :: "r"(dst), "l"(src) : "memory");
}
__device__ __forceinline__ void cp_commit() { asm volatile("cp.async.commit_group;" ::: "memory"); }
__device__ __forceinline__ void cp_wait0()  { asm volatile("cp.async.wait_group 0;" ::: "memory"); }
__device__ __forceinline__ uint32_t swz(int r, int u) {   // 128B rows, 16B units
    return (uint32_t)(r * 128 + ((u ^ (r & 7)) << 4));
}
__device__ __forceinline__ void cvt_hl(float4 v, uint2& hi, uint2& lo) {
    __half2 h01 = __floats2half2_rn(v.x, v.y);
    __half2 h23 = __floats2half2_rn(v.z, v.w);
    __half2 l01 = __floats2half2_rn(v.x - __low2float(h01), v.y - __high2float(h01));
    __half2 l23 = __floats2half2_rn(v.z - __low2float(h23), v.w - __high2float(h23));
    hi.x = *reinterpret_cast<uint32_t*>(&h01); hi.y = *reinterpret_cast<uint32_t*>(&h23);
    lo.x = *reinterpret_cast<uint32_t*>(&l01); lo.y = *reinterpret_cast<uint32_t*>(&l23);
}

// ---------------- pre-conversion ----------------
__global__ void precvt_w3(const float* __restrict__ Wo) {
    const int idx = blockIdx.x * blockDim.x + threadIdx.x;
    float4 v = *(const float4*)(Wo + (size_t)idx * 4);
    uint2 h, l;
    cvt_hl(v, h, l);
    *(uint2*)((char*)g_w3h + (size_t)idx * 8) = h;
    *(uint2*)((char*)g_w3l + (size_t)idx * 8) = l;
}
__global__ void precvt_w1(const float* __restrict__ Wq, const float* __restrict__ Wk,
                          const float* __restrict__ Wv) {
    const int idx = blockIdx.x * blockDim.x + threadIdx.x;
    const int w = blockIdx.y;
    const float* src = (w == 0) ? Wq : (w == 1) ? Wk : Wv;
    float4 v = *(const float4*)(src + (size_t)idx * 4);
    __half2 h01 = __floats2half2_rn(v.x, v.y);
    __half2 h23 = __floats2half2_rn(v.z, v.w);
    uint2 h = { *reinterpret_cast<uint32_t*>(&h01), *reinterpret_cast<uint32_t*>(&h23) };
    *(uint2*)((char*)g_w1[w] + (size_t)idx * 8) = h;
}

// ---------------- 1-term GEMM (q/k/v projections) -> fp16 out ----------------
__global__ void __launch_bounds__(512)
gemm1(const float* __restrict__ Xq, const float* __restrict__ Xk,
      const float* __restrict__ Xv, const float* __restrict__ bq,
      const float* __restrict__ bk, const float* __restrict__ bv)
{
    extern __shared__ char smem[];
    const int z = blockIdx.z;
    const float* X = (z == 0) ? Xq : (z == 1) ? Xk : Xv;
    const float* bias = (z == 0) ? bq : (z == 1) ? bk : bv;
    const __half* W = g_w1[z];
    __half* Y = (z == 0) ? g_qhh : (z == 1) ? g_khh : g_vhh;
    const int act = (z < 2);

    const int AHI = 0, BHI = TILEB, STAGE = 2*TILEB;
    const uint32_t sb = smem_u32(smem);
    const int tid = threadIdx.x;
    const int wid = tid >> 5, lane = tid & 31;
    const int wm = wid >> 2, wn = wid & 3;
    const int g = lane >> 2, tg = lane & 3;
    const int m0 = blockIdx.y * 128, n0 = blockIdx.x * 128;

    float acc[2][4][4];
#pragma unroll
    for (int i = 0; i < 2; i++)
#pragma unroll
        for (int j = 0; j < 4; j++)
#pragma unroll
            for (int r = 0; r < 4; r++) acc[i][j][r] = 0.f;

    float4 ra[4];
    auto ldgA = [&](int k0) {
#pragma unroll
        for (int it = 0; it < 4; it++) {
            int f = it * 512 + tid, r = f >> 4, cs = f & 15;
            ra[it] = *(const float4*)(X + (size_t)(m0 + r) * DDIM + k0 + cs * 4);
        }
    };
    auto stsA = [&](int stage) {
        char* base = smem + stage * STAGE + AHI;
#pragma unroll
        for (int it = 0; it < 4; it++) {
            int f = it * 512 + tid, r = f >> 4, cs = f & 15;
            __half2 h01 = __floats2half2_rn(ra[it].x, ra[it].y);
            __half2 h23 = __floats2half2_rn(ra[it].z, ra[it].w);
            uint2 h = { *reinterpret_cast<uint32_t*>(&h01), *reinterpret_cast<uint32_t*>(&h23) };
            *(uint2*)(base + (int)swz(r, cs >> 1) + (cs & 1) * 8) = h;
        }
    };
    auto issueB = [&](int stage, int kc) {
        const uint32_t stb = sb + stage * STAGE + BHI;
        const int k0 = kc * KC;
#pragma unroll
        for (int it = 0; it < 2; it++) {
            int f = it * 512 + tid, r = f >> 3, u = f & 7;
            cpasync16(stb + swz(r, u), (const char*)(W + (size_t)(n0 + r) * DDIM + k0) + u * 16);
        }
        cp_commit();
    };

    ldgA(0); issueB(0, 0); stsA(0); ldgA(KC);

    for (int kc = 0; kc < NCH; kc++) {
        const int cur = kc & 1;
        cp_wait0();
        __syncthreads();
        if (kc < NCH - 1) { issueB(1 - cur, kc + 1); stsA(1 - cur); }
        if (kc < NCH - 2) ldgA((kc + 2) * KC);

        const uint32_t st = sb + cur * STAGE;
#pragma unroll
        for (int ks = 0; ks < 4; ks++) {
            uint32_t ah[2][4];
#pragma unroll
            for (int mi = 0; mi < 2; mi++) {
                int rA = wm * 32 + mi * 16 + (lane & 15);
                int cA = ks * 2 + (lane >> 4);
                ldsm4(ah[mi], st + AHI + swz(rA, cA));
            }
#pragma unroll
            for (int np = 0; np < 2; np++) {
                int rB = wn * 32 + np * 16 + ((lane >> 4) << 3) + (lane & 7);
                int cB = ks * 2 + ((lane >> 3) & 1);
                uint32_t r4[4];
                ldsm4(r4, st + BHI + swz(rB, cB));
                uint32_t b0[2] = {r4[0], r4[1]}, b1[2] = {r4[2], r4[3]};
#pragma unroll
                for (int mi = 0; mi < 2; mi++) {
                    mma_f16(acc[mi][np*2+0], ah[mi], b0);
                    mma_f16(acc[mi][np*2+1], ah[mi], b1);
                }
            }
        }
        __syncthreads();
    }

#pragma unroll
    for (int mi = 0; mi < 2; mi++)
#pragma unroll
        for (int ni = 0; ni < 4; ni++) {
            const int col = n0 + wn * 32 + ni * 8 + tg * 2;
            const float b0 = bias[col], b1 = bias[col + 1];
#pragma unroll
            for (int half = 0; half < 2; half++) {
                const int row = m0 + wm * 32 + mi * 16 + g + half * 8;
                float x = acc[mi][ni][half * 2 + 0] + b0;
                float y = acc[mi][ni][half * 2 + 1] + b1;
                if (act) {
                    x = (x > 0.f) ? x + 1.f : expf(x);
                    y = (y > 0.f) ? y + 1.f : expf(y);
                }
                __half2 h = __floats2half2_rn(x, y);
                *(uint32_t*)((char*)Y + ((size_t)row * DDIM + col) * 2) =
                    *reinterpret_cast<uint32_t*>(&h);
            }
        }
}

// ---------------- 3-term GEMM (o-proj only) ----------------
__global__ void __launch_bounds__(512)
gemm3(const float* __restrict__ bias, float* __restrict__ Y)
{
    extern __shared__ char smem[];
    const float* X = g_att;
    const __half* whi = g_w3h;
    const __half* wlo = g_w3l;

    const int AHI = 0, ALO = TILEB, BHI = 2*TILEB, BLO = 3*TILEB, STAGE = 4*TILEB;
    const uint32_t sb = smem_u32(smem);
    const int tid = threadIdx.x;
    const int wid = tid >> 5, lane = tid & 31;
    const int wm = wid >> 2, wn = wid & 3;
    const int g = lane >> 2, tg = lane & 3;
    const int m0 = blockIdx.y * 128, n0 = blockIdx.x * 128;

    float acc[2][4][4];
#pragma unroll
    for (int i = 0; i < 2; i++)
#pragma unroll
        for (int j = 0; j < 4; j++)
#pragma unroll
            for (int r = 0; r < 4; r++) acc[i][j][r] = 0.f;

    float4 ra[4];
    auto ldgA = [&](int k0) {
#pragma unroll
        for (int it = 0; it < 4; it++) {
            int f = it * 512 + tid, r = f >> 4, cs = f & 15;
            ra[it] = *(const float4*)(X + (size_t)(m0 + r) * DDIM + k0 + cs * 4);
        }
    };
    auto stsA = [&](int stage) {
        char* base = smem + stage * STAGE;
#pragma unroll
        for (int it = 0; it < 4; it++) {
            int f = it * 512 + tid, r = f >> 4, cs = f & 15;
            int off = (int)swz(r, cs >> 1) + (cs & 1) * 8;
            uint2 h, l;
            cvt_hl(ra[it], h, l);
            *(uint2*)(base + AHI + off) = h;
            *(uint2*)(base + ALO + off) = l;
        }
    };
    auto issueB = [&](int stage, int kc) {
        const uint32_t stb = sb + stage * STAGE;
        const int k0 = kc * KC;
#pragma unroll
        for (int it = 0; it < 2; it++) {
            int f = it * 512 + tid, r = f >> 3, u = f & 7;
            cpasync16(stb + BHI + swz(r, u), (const char*)(whi + (size_t)(n0 + r) * DDIM + k0) + u * 16);
            cpasync16(stb + BLO + swz(r, u), (const char*)(wlo + (size_t)(n0 + r) * DDIM + k0) + u * 16);
        }
        cp_commit();
    };

    ldgA(0); issueB(0, 0); stsA(0); ldgA(KC);

    for (int kc = 0; kc < NCH; kc++) {
        const int cur = kc & 1;
        cp_wait0();
        __syncthreads();
        if (kc < NCH - 1) { issueB(1 - cur, kc + 1); stsA(1 - cur); }
        if (kc < NCH - 2) ldgA((kc + 2) * KC);

        const uint32_t st = sb + cur * STAGE;
#pragma unroll
        for (int ks = 0; ks < 4; ks++) {
            uint32_t ah[2][4], al[2][4];
#pragma unroll
            for (int mi = 0; mi < 2; mi++) {
                int rA = wm * 32 + mi * 16 + (lane & 15);
                int cA = ks * 2 + (lane >> 4);
                uint32_t ad = st + AHI + swz(rA, cA);
                ldsm4(ah[mi], ad);
                ldsm4(al[mi], ad + TILEB);
            }
            uint32_t bh[4][2], bl[4][2];
#pragma unroll
            for (int np = 0; np < 2; np++) {
                int rB = wn * 32 + np * 16 + ((lane >> 4) << 3) + (lane & 7);
                int cB = ks * 2 + ((lane >> 3) & 1);
                uint32_t bd = st + BHI + swz(rB, cB);
                uint32_t r4[4];
                ldsm4(r4, bd);
                bh[np*2][0] = r4[0]; bh[np*2][1] = r4[1];
                bh[np*2+1][0] = r4[2]; bh[np*2+1][1] = r4[3];
                ldsm4(r4, bd + TILEB);
                bl[np*2][0] = r4[0]; bl[np*2][1] = r4[1];
                bl[np*2+1][0] = r4[2]; bl[np*2+1][1] = r4[3];
            }
#pragma unroll
            for (int mi = 0; mi < 2; mi++)
#pragma unroll
                for (int ni = 0; ni < 4; ni++) {
                    mma_f16(acc[mi][ni], ah[mi], bh[ni]);
                    mma_f16(acc[mi][ni], ah[mi], bl[ni]);
                    mma_f16(acc[mi][ni], al[mi], bh[ni]);
                }
        }
        __syncthreads();
    }

#pragma unroll
    for (int mi = 0; mi < 2; mi++)
#pragma unroll
        for (int ni = 0; ni < 4; ni++) {
            const int col = n0 + wn * 32 + ni * 8 + tg * 2;
            const float b0 = bias[col], b1 = bias[col + 1];
#pragma unroll
            for (int half = 0; half < 2; half++) {
                const int row = m0 + wm * 32 + mi * 16 + g + half * 8;
                float2 o;
                o.x = acc[mi][ni][half * 2 + 0] + b0;
                o.y = acc[mi][ni][half * 2 + 1] + b1;
                *(float2*)(Y + (size_t)row * DDIM + col) = o;
            }
        }
}

// ---------------- zero ----------------
__global__ void zero_kernel()
{
    int i = blockIdx.x * blockDim.x + threadIdx.x;
    if (i < BB*HH*DH*DH) g_ctx[i]  = 0.f;
    if (i < BB*HH*DH)    g_ksum[i] = 0.f;
}

// ---------------- ctx: reads fp16 kh/vh ----------------
__global__ __launch_bounds__(256)
void ctx_kernel()
{
    const int bh = blockIdx.x;
    const int chunk = blockIdx.y;
    const int b = bh >> 3, h = bh & 7;

    __shared__ float ks[32][64];
    __shared__ float vs[32][64];

    const int tid = threadIdx.x;
    const int cb = tid >> 4;
    const int db = tid & 15;

    float acc[4][4];
#pragma unroll
    for (int i = 0; i < 4; i++)
#pragma unroll
        for (int j = 0; j < 4; j++) acc[i][j] = 0.f;
    float ksacc = 0.f;

    const int tbase = b*TT + chunk * (TT/NCHUNK);

    for (int tt = 0; tt < TT/NCHUNK; tt += 32) {
#pragma unroll
        for (int qq = 0; qq < 2; qq++) {
            const int fi = qq*256 + tid;
            const int r  = fi >> 4;
            const int c4 = fi & 15;
            const size_t gofs = (size_t)(tbase + tt + r) * DDIM + h*DH + c4*4;
            uint2 kw = *(const uint2*)((const char*)g_khh + gofs*2);
            uint2 vw = *(const uint2*)((const char*)g_vhh + gofs*2);
            float2 k0 = __half22float2(*reinterpret_cast<__half2*>(&kw.x));
            float2 k1 = __half22float2(*reinterpret_cast<__half2*>(&kw.y));
            float2 v0 = __half22float2(*reinterpret_cast<__half2*>(&vw.x));
            float2 v1 = __half22float2(*reinterpret_cast<__half2*>(&vw.y));
            ks[r][c4*4+0]=k0.x; ks[r][c4*4+1]=k0.y; ks[r][c4*4+2]=k1.x; ks[r][c4*4+3]=k1.y;
            vs[r][c4*4+0]=v0.x; vs[r][c4*4+1]=v0.y; vs[r][c4*4+2]=v1.x; vs[r][c4*4+3]=v1.y;
        }
        __syncthreads();

        if (tid < 64) {
#pragma unroll
            for (int t = 0; t < 32; t++) ksacc += ks[t][tid];
        }

#pragma unroll 8
        for (int t = 0; t < 32; t++) {
            float4 av = *(const float4*)&ks[t][cb*4];
            float4 bv = *(const float4*)&vs[t][db*4];
            float ar[4] = {av.x, av.y, av.z, av.w};
            float br[4] = {bv.x, bv.y, bv.z, bv.w};
#pragma unroll
            for (int i = 0; i < 4; i++)
#pragma unroll
                for (int j = 0; j < 4; j++)
                    acc[i][j] += ar[i] * br[j];
        }
        __syncthreads();
    }

    float* cp = g_ctx + bh * DH * DH;
#pragma unroll
    for (int i = 0; i < 4; i++)
#pragma unroll
        for (int j = 0; j < 4; j++)
            atomicAdd(&cp[(cb*4+i)*DH + (db*4+j)], acc[i][j]);
    if (tid < 64) atomicAdd(&g_ksum[bh*DH + tid], ksacc);
}

// ---------------- apply: att = (qh@ctx)/(qh@ksum), qh fp16 ----------------
__global__ __launch_bounds__(256)
void apply_kernel()
{
    const int bh = blockIdx.x;
    const int tile = blockIdx.y;
    const int b = bh >> 3, h = bh & 7;

    __shared__ float ctxs[64][68];
    __shared__ float qsm[64][68];
    __shared__ float dsm[64];

    const int tid = threadIdx.x;
    const int t0 = tile * 64;
    const float* cp = g_ctx + bh * 4096;

#pragma unroll
    for (int qq = 0; qq < 4; qq++) {
        const int fi = qq*256 + tid;
        const int r  = fi >> 4;
        const int c4 = fi & 15;
        *(float4*)&ctxs[r][c4*4] = *(const float4*)(cp + r*64 + c4*4);
        const size_t gofs = (size_t)(b*TT + t0 + r) * DDIM + h*DH + c4*4;
        uint2 qw = *(const uint2*)((const char*)g_qhh + gofs*2);
        float2 q0 = __half22float2(*reinterpret_cast<__half2*>(&qw.x));
        float2 q1 = __half22float2(*reinterpret_cast<__half2*>(&qw.y));
        qsm[r][c4*4+0]=q0.x; qsm[r][c4*4+1]=q0.y; qsm[r][c4*4+2]=q1.x; qsm[r][c4*4+3]=q1.y;
    }
    __syncthreads();

    if (tid < 64) {
        const float* kp = g_ksum + bh * DH;
        float dn = 0.f;
#pragma unroll
        for (int c = 0; c < 64; c++) dn += qsm[tid][c] * kp[c];
        dsm[tid] = dn;
    }
    __syncthreads();

    const int tsub = tid >> 4;
    const int dq   = (tid & 15) * 4;
#pragma unroll
    for (int ts = 0; ts < 4; ts++) {
        const int t = ts*16 + tsub;
        float4 acc = {0.f, 0.f, 0.f, 0.f};
#pragma unroll
        for (int c = 0; c < 64; c++) {
            const float qv = qsm[t][c];
            const float4 cv = *(const float4*)&ctxs[c][dq];
            acc.x += qv * cv.x;
            acc.y += qv * cv.y;
            acc.z += qv * cv.z;
            acc.w += qv * cv.w;
        }
        const float inv = 1.f / dsm[t];
        float4 o = {acc.x*inv, acc.y*inv, acc.z*inv, acc.w*inv};
        const size_t gofs = (size_t)(b*TT + t0 + t) * DDIM + h*DH + dq;
        *(float4*)(g_att + gofs) = o;
    }
}

// ---------------- launch ----------------
extern "C" void kernel_launch(void* const* d_in, const int* in_sizes, int n_in,
                              void* d_out, int out_size)
{
    const float* q  = (const float*)d_in[0];
    const float* k  = (const float*)d_in[1];
    const float* v  = (const float*)d_in[2];
    const float* Wq = (const float*)d_in[3];
    const float* bq = (const float*)d_in[4];
    const float* Wk = (const float*)d_in[5];
    const float* bk = (const float*)d_in[6];
    const float* Wv = (const float*)d_in[7];
    const float* bv = (const float*)d_in[8];
    const float* Wo = (const float*)d_in[9];
    const float* bo = (const float*)d_in[10];
    float* out = (float*)d_out;

    cudaFuncSetAttribute((const void*)gemm3, cudaFuncAttributeMaxDynamicSharedMemorySize, SM3);
    cudaFuncSetAttribute((const void*)gemm1, cudaFuncAttributeMaxDynamicSharedMemorySize, SM1);

    precvt_w3<<<256, 256>>>(Wo);
    precvt_w1<<<dim3(256, 3), 256>>>(Wq, Wk, Wv);
    zero_kernel<<<(BB*HH*DH*DH + 255)/256, 256>>>();
    gemm1<<<dim3(4, 256, 3), 512, SM1>>>(q, k, v, bq, bk, bv);   // qh/kh/vh 1-term fp16
    ctx_kernel<<<dim3(BB*HH, NCHUNK), 256>>>();
    apply_kernel<<<dim3(BB*HH, TT/64), 256>>>();
    gemm3<<<dim3(4, 256), 512, SM3>>>(bo, out);                  // out 3-term
}

// round 9
// speedup vs baseline: 2.1436x; 1.0726x over previous
#include <cuda_runtime.h>
#include <cuda_fp16.h>
#include <math.h>
#include <stdint.h>

#define BB 4
#define TT 8192
#define DDIM 512
#define HH 8
#define DH 64
#define MM (BB*TT)
#define NCHUNK 32

#define KC 64                    // halves per K chunk (128B rows)
#define NCH (DDIM/KC)            // 8
#define TILEB (128*128)          // 16 KB (128 rows x 128B)
#define SM3 (2*4*TILEB)          // gemm3: 2 stages x (Ahi,Alo,Bhi,Blo) = 128 KB
// gemm1: A 128r (16 KB) + B 256r (32 KB) per stage, 2 stages = 96 KB
#define G1_A 0
#define G1_B TILEB
#define G1_STAGE (3*TILEB)
#define SM1 (2*G1_STAGE)

// Scratch
__device__ float g_att[(size_t)MM*DDIM];
__device__ __half g_qhh[(size_t)MM*DDIM];
__device__ __half g_khh[(size_t)MM*DDIM];
__device__ __half g_vhh[(size_t)MM*DDIM];
__device__ float g_ctx[BB*HH*DH*DH];
__device__ float g_ksum[BB*HH*DH];
__device__ __half g_w3h[DDIM*DDIM];      // Wo hi
__device__ __half g_w3l[DDIM*DDIM];      // Wo lo
__device__ __half g_w1[3][DDIM*DDIM];    // Wq, Wk, Wv single fp16

// ---------------- helpers ----------------
__device__ __forceinline__ uint32_t smem_u32(const void* p) {
    uint32_t a;
    asm("{ .reg .u64 t; cvta.to.shared.u64 t, %1; cvt.u32.u64 %0, t; }" : "=r"(a) : "l"(p));
    return a;
}
__device__ __forceinline__ void ldsm4(uint32_t* r, uint32_t addr) {
    asm volatile("ldmatrix.sync.aligned.m8n8.x4.shared.b16 {%0,%1,%2,%3}, [%4];"
                 : "=r"(r[0]), "=r"(r[1]), "=r"(r[2]), "=r"(r[3]) : "r"(addr));
}
__device__ __forceinline__ void mma_f16(float* c, const uint32_t* a, const uint32_t* b) {
    asm volatile("mma.sync.aligned.m16n8k16.row.col.f32.f16.f16.f32 "
                 "{%0,%1,%2,%3}, {%4,%5,%6,%7}, {%8,%9}, {%0,%1,%2,%3};"
                 : "+f"(c[0]), "+f"(c[1]), "+f"(c[2]), "+f"(c[3])
                 : "r"(a[0]), "r"(a[1]), "r"(a[2]), "r"(a[3]), "r"(b[0]), "r"(b[1]));
}
__device__ __forceinline__ void cpasync16(uint32_t dst, const void* src) {
    asm volatile("cp.async.cg.shared.global [%0], [%1], 16;" :: "r"(dst), "l"(src) : "memory");
}
__device__ __forceinline__ void cp_commit() { asm volatile("cp.async.commit_group;" ::: "memory"); }
__device__ __forceinline__ void cp_wait0()  { asm volatile("cp.async.wait_group 0;" ::: "memory"); }
__device__ __forceinline__ uint32_t swz(int r, int u) {   // 128B rows, 16B units
    return (uint32_t)(r * 128 + ((u ^ (r & 7)) << 4));
}
// XOR base for a row: swz(r,u) == sbase(r) ^ (u<<4)
__device__ __forceinline__ uint32_t sbase(int r) {
    return (uint32_t)(r * 128 + ((r & 7) << 4));
}
__device__ __forceinline__ void cvt_hl(float4 v, uint2& hi, uint2& lo) {
    __half2 h01 = __floats2half2_rn(v.x, v.y);
    __half2 h23 = __floats2half2_rn(v.z, v.w);
    __half2 l01 = __floats2half2_rn(v.x - __low2float(h01), v.y - __high2float(h01));
    __half2 l23 = __floats2half2_rn(v.z - __low2float(h23), v.w - __high2float(h23));
    hi.x = *reinterpret_cast<uint32_t*>(&h01); hi.y = *reinterpret_cast<uint32_t*>(&h23);
    lo.x = *reinterpret_cast<uint32_t*>(&l01); lo.y = *reinterpret_cast<uint32_t*>(&l23);
}

// ---------------- pre-conversion ----------------
__global__ void precvt_w3(const float* __restrict__ Wo) {
    const int idx = blockIdx.x * blockDim.x + threadIdx.x;
    float4 v = *(const float4*)(Wo + (size_t)idx * 4);
    uint2 h, l;
    cvt_hl(v, h, l);
    *(uint2*)((char*)g_w3h + (size_t)idx * 8) = h;
    *(uint2*)((char*)g_w3l + (size_t)idx * 8) = l;
}
__global__ void precvt_w1(const float* __restrict__ Wq, const float* __restrict__ Wk,
                          const float* __restrict__ Wv) {
    const int idx = blockIdx.x * blockDim.x + threadIdx.x;
    const int w = blockIdx.y;
    const float* src = (w == 0) ? Wq : (w == 1) ? Wk : Wv;
    float4 v = *(const float4*)(src + (size_t)idx * 4);
    __half2 h01 = __floats2half2_rn(v.x, v.y);
    __half2 h23 = __floats2half2_rn(v.z, v.w);
    uint2 h = { *reinterpret_cast<uint32_t*>(&h01), *reinterpret_cast<uint32_t*>(&h23) };
    *(uint2*)((char*)g_w1[w] + (size_t)idx * 8) = h;
}

// ---------------- 1-term GEMM (q/k/v) -> fp16 out ----------------
// CTA 128x256, 512 thr, warp tile 32x64 (4x4 warps). XOR-hoisted swizzle.
__global__ void __launch_bounds__(512)
gemm1(const float* __restrict__ Xq, const float* __restrict__ Xk,
      const float* __restrict__ Xv, const float* __restrict__ bq,
      const float* __restrict__ bk, const float* __restrict__ bv)
{
    extern __shared__ char smem[];
    const int z = blockIdx.z;
    const float* X = (z == 0) ? Xq : (z == 1) ? Xk : Xv;
    const float* bias = (z == 0) ? bq : (z == 1) ? bk : bv;
    const __half* W = g_w1[z];
    __half* Y = (z == 0) ? g_qhh : (z == 1) ? g_khh : g_vhh;
    const int act = (z < 2);

    const uint32_t sb = smem_u32(smem);
    const int tid = threadIdx.x;
    const int wid = tid >> 5, lane = tid & 31;
    const int wm = wid >> 2, wn = wid & 3;       // 4 m-warps x 4 n-warps
    const int g = lane >> 2, tg = lane & 3;
    const int m0 = blockIdx.y * 128, n0 = blockIdx.x * 256;

    float acc[2][8][4];
#pragma unroll
    for (int i = 0; i < 2; i++)
#pragma unroll
        for (int j = 0; j < 8; j++)
#pragma unroll
            for (int r = 0; r < 4; r++) acc[i][j][r] = 0.f;

    // hoisted ldsm XOR-bases (offsets within a stage)
    uint32_t aB[2], bB[4];
#pragma unroll
    for (int mi = 0; mi < 2; mi++) {
        int rA = wm * 32 + mi * 16 + (lane & 15);
        aB[mi] = G1_A + sbase(rA) ^ 0;  // parenthesize carefully below
        aB[mi] = (uint32_t)G1_A + sbase(rA);
    }
#pragma unroll
    for (int np = 0; np < 4; np++) {
        int rB = wn * 64 + np * 16 + ((lane >> 4) << 3) + (lane & 7);
        bB[np] = (uint32_t)G1_B + sbase(rB);
    }
    const uint32_t aX = (uint32_t)(lane >> 4) << 4;        // cA bit0 component
    const uint32_t bX = (uint32_t)((lane >> 3) & 1) << 4;  // cB bit0 component

    float4 ra[4];
    auto ldgA = [&](int k0) {
#pragma unroll
        for (int it = 0; it < 4; it++) {
            int f = it * 512 + tid, r = f >> 4, cs = f & 15;
            ra[it] = *(const float4*)(X + (size_t)(m0 + r) * DDIM + k0 + cs * 4);
        }
    };
    auto stsA = [&](int stage) {
        char* base = smem + stage * G1_STAGE + G1_A;
#pragma unroll
        for (int it = 0; it < 4; it++) {
            int f = it * 512 + tid, r = f >> 4, cs = f & 15;
            __half2 h01 = __floats2half2_rn(ra[it].x, ra[it].y);
            __half2 h23 = __floats2half2_rn(ra[it].z, ra[it].w);
            uint2 h = { *reinterpret_cast<uint32_t*>(&h01), *reinterpret_cast<uint32_t*>(&h23) };
            *(uint2*)(base + (int)swz(r, cs >> 1) + (cs & 1) * 8) = h;
        }
    };
    auto issueB = [&](int stage, int kc) {
        const uint32_t stb = sb + stage * G1_STAGE + G1_B;
        const int k0 = kc * KC;
#pragma unroll
        for (int it = 0; it < 4; it++) {
            int f = it * 512 + tid, r = f >> 3, u = f & 7;
            cpasync16(stb + swz(r, u), (const char*)(W + (size_t)(n0 + r) * DDIM + k0) + u * 16);
        }
        cp_commit();
    };

    ldgA(0); issueB(0, 0); stsA(0); ldgA(KC);

    for (int kc = 0; kc < NCH; kc++) {
        const int cur = kc & 1;
        cp_wait0();
        __syncthreads();
        if (kc < NCH - 1) { issueB(1 - cur, kc + 1); stsA(1 - cur); }
        if (kc < NCH - 2) ldgA((kc + 2) * KC);

        const uint32_t st = sb + cur * G1_STAGE;
#pragma unroll
        for (int ks = 0; ks < 4; ks++) {
            const uint32_t kx = (uint32_t)(ks * 2) << 4;
            uint32_t ah[2][4];
#pragma unroll
            for (int mi = 0; mi < 2; mi++)
                ldsm4(ah[mi], st + (aB[mi] ^ (kx | aX)));
#pragma unroll
            for (int np = 0; np < 4; np++) {
                uint32_t r4[4];
                ldsm4(r4, st + (bB[np] ^ (kx | bX)));
                uint32_t b0[2] = {r4[0], r4[1]}, b1[2] = {r4[2], r4[3]};
#pragma unroll
                for (int mi = 0; mi < 2; mi++) {
                    mma_f16(acc[mi][np*2+0], ah[mi], b0);
                    mma_f16(acc[mi][np*2+1], ah[mi], b1);
                }
            }
        }
        __syncthreads();
    }

#pragma unroll
    for (int mi = 0; mi < 2; mi++)
#pragma unroll
        for (int ni = 0; ni < 8; ni++) {
            const int col = n0 + wn * 64 + ni * 8 + tg * 2;
            const float b0 = bias[col], b1 = bias[col + 1];
#pragma unroll
            for (int half = 0; half < 2; half++) {
                const int row = m0 + wm * 32 + mi * 16 + g + half * 8;
                float x = acc[mi][ni][half * 2 + 0] + b0;
                float y = acc[mi][ni][half * 2 + 1] + b1;
                if (act) {
                    x = (x > 0.f) ? x + 1.f : expf(x);
                    y = (y > 0.f) ? y + 1.f : expf(y);
                }
                __half2 h = __floats2half2_rn(x, y);
                *(uint32_t*)((char*)Y + ((size_t)row * DDIM + col) * 2) =
                    *reinterpret_cast<uint32_t*>(&h);
            }
        }
}

// ---------------- 3-term GEMM (o-proj only) ----------------
__global__ void __launch_bounds__(512)
gemm3(const float* __restrict__ bias, float* __restrict__ Y)
{
    extern __shared__ char smem[];
    const float* X = g_att;
    const __half* whi = g_w3h;
    const __half* wlo = g_w3l;

    const int AHI = 0, ALO = TILEB, BHI = 2*TILEB, BLO = 3*TILEB, STAGE = 4*TILEB;
    const uint32_t sb = smem_u32(smem);
    const int tid = threadIdx.x;
    const int wid = tid >> 5, lane = tid & 31;
    const int wm = wid >> 2, wn = wid & 3;
    const int g = lane >> 2, tg = lane & 3;
    const int m0 = blockIdx.y * 128, n0 = blockIdx.x * 128;

    float acc[2][4][4];
#pragma unroll
    for (int i = 0; i < 2; i++)
#pragma unroll
        for (int j = 0; j < 4; j++)
#pragma unroll
            for (int r = 0; r < 4; r++) acc[i][j][r] = 0.f;

    float4 ra[4];
    auto ldgA = [&](int k0) {
#pragma unroll
        for (int it = 0; it < 4; it++) {
            int f = it * 512 + tid, r = f >> 4, cs = f & 15;
            ra[it] = *(const float4*)(X + (size_t)(m0 + r) * DDIM + k0 + cs * 4);
        }
    };
    auto stsA = [&](int stage) {
        char* base = smem + stage * STAGE;
#pragma unroll
        for (int it = 0; it < 4; it++) {
            int f = it * 512 + tid, r = f >> 4, cs = f & 15;
            int off = (int)swz(r, cs >> 1) + (cs & 1) * 8;
            uint2 h, l;
            cvt_hl(ra[it], h, l);
            *(uint2*)(base + AHI + off) = h;
            *(uint2*)(base + ALO + off) = l;
        }
    };
    auto issueB = [&](int stage, int kc) {
        const uint32_t stb = sb + stage * STAGE;
        const int k0 = kc * KC;
#pragma unroll
        for (int it = 0; it < 2; it++) {
            int f = it * 512 + tid, r = f >> 3, u = f & 7;
            cpasync16(stb + BHI + swz(r, u), (const char*)(whi + (size_t)(n0 + r) * DDIM + k0) + u * 16);
            cpasync16(stb + BLO + swz(r, u), (const char*)(wlo + (size_t)(n0 + r) * DDIM + k0) + u * 16);
        }
        cp_commit();
    };

    ldgA(0); issueB(0, 0); stsA(0); ldgA(KC);

    for (int kc = 0; kc < NCH; kc++) {
        const int cur = kc & 1;
        cp_wait0();
        __syncthreads();
        if (kc < NCH - 1) { issueB(1 - cur, kc + 1); stsA(1 - cur); }
        if (kc < NCH - 2) ldgA((kc + 2) * KC);

        const uint32_t st = sb + cur * STAGE;
#pragma unroll
        for (int ks = 0; ks < 4; ks++) {
            uint32_t ah[2][4], al[2][4];
#pragma unroll
            for (int mi = 0; mi < 2; mi++) {
                int rA = wm * 32 + mi * 16 + (lane & 15);
                int cA = ks * 2 + (lane >> 4);
                uint32_t ad = st + AHI + swz(rA, cA);
                ldsm4(ah[mi], ad);
                ldsm4(al[mi], ad + TILEB);
            }
            uint32_t bh[4][2], bl[4][2];
#pragma unroll
            for (int np = 0; np < 2; np++) {
                int rB = wn * 32 + np * 16 + ((lane >> 4) << 3) + (lane & 7);
                int cB = ks * 2 + ((lane >> 3) & 1);
                uint32_t bd = st + BHI + swz(rB, cB);
                uint32_t r4[4];
                ldsm4(r4, bd);
                bh[np*2][0] = r4[0]; bh[np*2][1] = r4[1];
                bh[np*2+1][0] = r4[2]; bh[np*2+1][1] = r4[3];
                ldsm4(r4, bd + TILEB);
                bl[np*2][0] = r4[0]; bl[np*2][1] = r4[1];
                bl[np*2+1][0] = r4[2]; bl[np*2+1][1] = r4[3];
            }
#pragma unroll
            for (int mi = 0; mi < 2; mi++)
#pragma unroll
                for (int ni = 0; ni < 4; ni++) {
                    mma_f16(acc[mi][ni], ah[mi], bh[ni]);
                    mma_f16(acc[mi][ni], ah[mi], bl[ni]);
                    mma_f16(acc[mi][ni], al[mi], bh[ni]);
                }
        }
        __syncthreads();
    }

#pragma unroll
    for (int mi = 0; mi < 2; mi++)
#pragma unroll
        for (int ni = 0; ni < 4; ni++) {
            const int col = n0 + wn * 32 + ni * 8 + tg * 2;
            const float b0 = bias[col], b1 = bias[col + 1];
#pragma unroll
            for (int half = 0; half < 2; half++) {
                const int row = m0 + wm * 32 + mi * 16 + g + half * 8;
                float2 o;
                o.x = acc[mi][ni][half * 2 + 0] + b0;
                o.y = acc[mi][ni][half * 2 + 1] + b1;
                *(float2*)(Y + (size_t)row * DDIM + col) = o;
            }
        }
}

// ---------------- zero ----------------
__global__ void zero_kernel()
{
    int i = blockIdx.x * blockDim.x + threadIdx.x;
    if (i < BB*HH*DH*DH) g_ctx[i]  = 0.f;
    if (i < BB*HH*DH)    g_ksum[i] = 0.f;
}

// ---------------- ctx: reads fp16 kh/vh ----------------
__global__ __launch_bounds__(256)
void ctx_kernel()
{
    const int bh = blockIdx.x;
    const int chunk = blockIdx.y;
    const int b = bh >> 3, h = bh & 7;

    __shared__ float ks[32][64];
    __shared__ float vs[32][64];

    const int tid = threadIdx.x;
    const int cb = tid >> 4;
    const int db = tid & 15;

    float acc[4][4];
#pragma unroll
    for (int i = 0; i < 4; i++)
#pragma unroll
        for (int j = 0; j < 4; j++) acc[i][j] = 0.f;
    float ksacc = 0.f;

    const int tbase = b*TT + chunk * (TT/NCHUNK);

    for (int tt = 0; tt < TT/NCHUNK; tt += 32) {
#pragma unroll
        for (int qq = 0; qq < 2; qq++) {
            const int fi = qq*256 + tid;
            const int r  = fi >> 4;
            const int c4 = fi & 15;
            const size_t gofs = (size_t)(tbase + tt + r) * DDIM + h*DH + c4*4;
            uint2 kw = *(const uint2*)((const char*)g_khh + gofs*2);
            uint2 vw = *(const uint2*)((const char*)g_vhh + gofs*2);
            float2 k0 = __half22float2(*reinterpret_cast<__half2*>(&kw.x));
            float2 k1 = __half22float2(*reinterpret_cast<__half2*>(&kw.y));
            float2 v0 = __half22float2(*reinterpret_cast<__half2*>(&vw.x));
            float2 v1 = __half22float2(*reinterpret_cast<__half2*>(&vw.y));
            ks[r][c4*4+0]=k0.x; ks[r][c4*4+1]=k0.y; ks[r][c4*4+2]=k1.x; ks[r][c4*4+3]=k1.y;
            vs[r][c4*4+0]=v0.x; vs[r][c4*4+1]=v0.y; vs[r][c4*4+2]=v1.x; vs[r][c4*4+3]=v1.y;
        }
        __syncthreads();

        if (tid < 64) {
#pragma unroll
            for (int t = 0; t < 32; t++) ksacc += ks[t][tid];
        }

#pragma unroll 8
        for (int t = 0; t < 32; t++) {
            float4 av = *(const float4*)&ks[t][cb*4];
            float4 bv = *(const float4*)&vs[t][db*4];
            float ar[4] = {av.x, av.y, av.z, av.w};
            float br[4] = {bv.x, bv.y, bv.z, bv.w};
#pragma unroll
            for (int i = 0; i < 4; i++)
#pragma unroll
                for (int j = 0; j < 4; j++)
                    acc[i][j] += ar[i] * br[j];
        }
        __syncthreads();
    }

    float* cp = g_ctx + bh * DH * DH;
#pragma unroll
    for (int i = 0; i < 4; i++)
#pragma unroll
        for (int j = 0; j < 4; j++)
            atomicAdd(&cp[(cb*4+i)*DH + (db*4+j)], acc[i][j]);
    if (tid < 64) atomicAdd(&g_ksum[bh*DH + tid], ksacc);
}

// ---------------- apply: att = (qh@ctx)/(qh@ksum), qh fp16 ----------------
__global__ __launch_bounds__(256)
void apply_kernel()
{
    const int bh = blockIdx.x;
    const int tile = blockIdx.y;
    const int b = bh >> 3, h = bh & 7;

    __shared__ float ctxs[64][68];
    __shared__ float qsm[64][68];
    __shared__ float dsm[64];

    const int tid = threadIdx.x;
    const int t0 = tile * 64;
    const float* cp = g_ctx + bh * 4096;

#pragma unroll
    for (int qq = 0; qq < 4; qq++) {
        const int fi = qq*256 + tid;
        const int r  = fi >> 4;
        const int c4 = fi & 15;
        *(float4*)&ctxs[r][c4*4] = *(const float4*)(cp + r*64 + c4*4);
        const size_t gofs = (size_t)(b*TT + t0 + r) * DDIM + h*DH + c4*4;
        uint2 qw = *(const uint2*)((const char*)g_qhh + gofs*2);
        float2 q0 = __half22float2(*reinterpret_cast<__half2*>(&qw.x));
        float2 q1 = __half22float2(*reinterpret_cast<__half2*>(&qw.y));
        qsm[r][c4*4+0]=q0.x; qsm[r][c4*4+1]=q0.y; qsm[r][c4*4+2]=q1.x; qsm[r][c4*4+3]=q1.y;
    }
    __syncthreads();

    if (tid < 64) {
        const float* kp = g_ksum + bh * DH;
        float dn = 0.f;
#pragma unroll
        for (int c = 0; c < 64; c++) dn += qsm[tid][c] * kp[c];
        dsm[tid] = dn;
    }
    __syncthreads();

    const int tsub = tid >> 4;
    const int dq   = (tid & 15) * 4;
#pragma unroll
    for (int ts = 0; ts < 4; ts++) {
        const int t = ts*16 + tsub;
        float4 acc = {0.f, 0.f, 0.f, 0.f};
#pragma unroll
        for (int c = 0; c < 64; c++) {
            const float qv = qsm[t][c];
            const float4 cv = *(const float4*)&ctxs[c][dq];
            acc.x += qv * cv.x;
            acc.y += qv * cv.y;
            acc.z += qv * cv.z;
            acc.w += qv * cv.w;
        }
        const float inv = 1.f / dsm[t];
        float4 o = {acc.x*inv, acc.y*inv, acc.z*inv, acc.w*inv};
        const size_t gofs = (size_t)(b*TT + t0 + t) * DDIM + h*DH + dq;
        *(float4*)(g_att + gofs) = o;
    }
}

// ---------------- launch ----------------
extern "C" void kernel_launch(void* const* d_in, const int* in_sizes, int n_in,
                              void* d_out, int out_size)
{
    const float* q  = (const float*)d_in[0];
    const float* k  = (const float*)d_in[1];
    const float* v  = (const float*)d_in[2];
    const float* Wq = (const float*)d_in[3];
    const float* bq = (const float*)d_in[4];
    const float* Wk = (const float*)d_in[5];
    const float* bk = (const float*)d_in[6];
    const float* Wv = (const float*)d_in[7];
    const float* bv = (const float*)d_in[8];
    const float* Wo = (const float*)d_in[9];
    const float* bo = (const float*)d_in[10];
    float* out = (float*)d_out;

    cudaFuncSetAttribute((const void*)gemm3, cudaFuncAttributeMaxDynamicSharedMemorySize, SM3);
    cudaFuncSetAttribute((const void*)gemm1, cudaFuncAttributeMaxDynamicSharedMemorySize, SM1);

    precvt_w3<<<256, 256>>>(Wo);
    precvt_w1<<<dim3(256, 3), 256>>>(Wq, Wk, Wv);
    zero_kernel<<<(BB*HH*DH*DH + 255)/256, 256>>>();
    gemm1<<<dim3(2, 256, 3), 512, SM1>>>(q, k, v, bq, bk, bv);   // qh/kh/vh 1-term fp16
    ctx_kernel<<<dim3(BB*HH, NCHUNK), 256>>>();
    apply_kernel<<<dim3(BB*HH, TT/64), 256>>>();
    gemm3<<<dim3(4, 256), 512, SM3>>>(bo, out);                  // out 3-term
}